// round 16
// baseline (speedup 1.0000x reference)
#include <cuda_runtime.h>
#include <cuda_fp16.h>

// ---------------- problem constants ----------------
#define N_NODES 20000
#define N_EDGES 160000
#define MEGA_NB 64

// ---------------- device scratch (static; no allocs) ----------------
// P̄[n, s, o]: s=0..7 edge-weight slots, s=8 = R (unit coefficient). fp16.
__device__ __align__(16) __half g_Ph[N_NODES * 360];  // max 9*40 cols
__device__ __align__(16) float g_AGG1[N_NODES * 40];
__device__ __align__(16) float g_AGG2[N_NODES * 24];
__device__ __align__(16) float g_AGG3[N_NODES * 24];
__device__ int   g_deg[N_NODES];    // zero at load; re-zeroed by k_mega each call
__device__ int   g_cursor[N_NODES];
__device__ int   g_bsum[40];
__device__ __align__(8)  int2   g_srt[N_EDGES];       // (src, tgt) sorted by src
__device__ __align__(16) __half g_eperm_h[N_EDGES * 8];  // e payload fp16, src-sorted
__device__ float g_poolpart[MEGA_NB * 24];
__device__ __align__(16) float g_v2[768];
__device__ __align__(16) float g_v3[512];
__device__ float g_v3r[64];
__device__ unsigned g_barS;    // scanAB barrier
__device__ unsigned g_barcnt;  // mega barrier
__device__ unsigned g_done;    // mega last-block ticket

// ---------------- helpers ----------------
__device__ __forceinline__ void ffma2(unsigned long long& d, unsigned long long a,
                                      unsigned long long b) {
    asm("fma.rn.f32x2 %0, %1, %2, %0;" : "+l"(d) : "l"(a), "l"(b));
}
__device__ __forceinline__ unsigned long long packf2(float x) {
    unsigned long long r;
    asm("mov.b64 %0, {%1, %1};" : "=l"(r) : "f"(x));
    return r;
}
__device__ __forceinline__ float2 unpackf2(unsigned long long v) {
    float2 f;
    asm("mov.b64 {%0, %1}, %2;" : "=f"(f.x), "=f"(f.y) : "l"(v));
    return f;
}
// unpack 8 fp16 (uint4) -> two float4
__device__ __forceinline__ void h8_to_f8(uint4 u, float4& a, float4& b) {
    float2 f0 = __half22float2(*reinterpret_cast<__half2*>(&u.x));
    float2 f1 = __half22float2(*reinterpret_cast<__half2*>(&u.y));
    float2 f2 = __half22float2(*reinterpret_cast<__half2*>(&u.z));
    float2 f3 = __half22float2(*reinterpret_cast<__half2*>(&u.w));
    a = make_float4(f0.x, f0.y, f1.x, f1.y);
    b = make_float4(f2.x, f2.y, f3.x, f3.y);
}
__device__ __forceinline__ void gridbar(unsigned* cnt, int& epoch, int nb) {
    __threadfence();
    __syncthreads();
    epoch++;
    if (threadIdx.x == 0) {
        atomicAdd(cnt, 1u);
        unsigned target = (unsigned)epoch * (unsigned)nb;
        while (*((volatile unsigned*)cnt) < target) __nanosleep(20);
    }
    __syncthreads();
}

// ---------------- k1: node1 (blocks 0..394) || hist (blocks 395..1019) ----------------
// node1: cols [0,360) P̄(fp16, incl. R at s=8), [360,400) AGG1(+bias).
__global__ __launch_bounds__(256) void k1_node1_hist(
    const float* __restrict__ xin,
    const float* __restrict__ We, const float* __restrict__ be,
    const float* __restrict__ root, const float* __restrict__ bias,
    const int2* __restrict__ ei)
{
    constexpr int FI = 16, FO = 40, CC = 5;
    constexpr int CC16 = CC * 16;
    __shared__ __align__(16) float Wsh[FI * CC16];
    __shared__ float bsh[FO];
    int t = threadIdx.x;
    int b = blockIdx.x;

    if (b >= 395) {   // histogram blocks (full 160k-thread parallelism)
        int i = (b - 395) * 256 + t;
        if (i < N_EDGES) atomicAdd(&g_deg[ei[i].x], 1);
        return;
    }

    int bx = b % 79;        // node tile
    int by = b / 79;        // col chunk
    int cg0 = by * CC;
    int colbase = cg0 * 16;

    if (b == 0 && t == 0) { g_barS = 0u; g_barcnt = 0u; g_done = 0u; }

    for (int idx = t; idx < FI * CC16; idx += 256) {
        int f = idx / CC16, cl = idx % CC16;
        int c = colbase + cl;
        float w;
        if (c < 8 * FO) {
            int s = c / FO, o = c % FO;
            w = We[s * (FI * FO) + f * FO + o];
        } else if (c < 9 * FO) {
            int o = c - 8 * FO;
            w = be[f * FO + o];
        } else {
            int o = c - 9 * FO;
            w = root[f * FO + o];
        }
        Wsh[idx] = w;
    }
    for (int idx = t; idx < FO; idx += 256) bsh[idx] = bias[idx];
    __syncthreads();

    int node = bx * 256 + t;
    if (node >= N_NODES) return;

    float h[FI];
    const float4* hv = reinterpret_cast<const float4*>(xin + (size_t)node * FI);
#pragma unroll
    for (int f4 = 0; f4 < FI / 4; f4++) {
        float4 a = hv[f4];
        h[4*f4+0]=a.x; h[4*f4+1]=a.y; h[4*f4+2]=a.z; h[4*f4+3]=a.w;
    }

    const ulonglong2* Wv = reinterpret_cast<const ulonglong2*>(Wsh);
    uint4* Pv = reinterpret_cast<uint4*>(g_Ph) + (size_t)node * (9 * FO / 8);
    float4* Av = reinterpret_cast<float4*>(g_AGG1) + (size_t)node * (FO / 4);

#pragma unroll
    for (int cg = 0; cg < CC; cg++) {
        unsigned long long acc[8];
#pragma unroll
        for (int k = 0; k < 8; k++) acc[k] = 0ull;
#pragma unroll
        for (int f = 0; f < FI; f++) {
            const ulonglong2* wrow = Wv + f * (CC * 4) + cg * 4;
            ulonglong2 wA = wrow[0], wB = wrow[1], wC = wrow[2], wD = wrow[3];
            unsigned long long ha = packf2(h[f]);
            ffma2(acc[0], ha, wA.x); ffma2(acc[1], ha, wA.y);
            ffma2(acc[2], ha, wB.x); ffma2(acc[3], ha, wB.y);
            ffma2(acc[4], ha, wC.x); ffma2(acc[5], ha, wC.y);
            ffma2(acc[6], ha, wD.x); ffma2(acc[7], ha, wD.y);
        }
#pragma unroll
        for (int q2 = 0; q2 < 2; q2++) {   // 8 cols per store group
            int cb = (cg0 + cg) * 16 + q2 * 8;
            float2 a0 = unpackf2(acc[4*q2+0]), a1 = unpackf2(acc[4*q2+1]);
            float2 a2 = unpackf2(acc[4*q2+2]), a3 = unpackf2(acc[4*q2+3]);
            if (cb < 9 * FO) {
                union { __half2 h2[4]; uint4 u; } pk;
                pk.h2[0] = __floats2half2_rn(a0.x, a0.y);
                pk.h2[1] = __floats2half2_rn(a1.x, a1.y);
                pk.h2[2] = __floats2half2_rn(a2.x, a2.y);
                pk.h2[3] = __floats2half2_rn(a3.x, a3.y);
                Pv[cb / 8] = pk.u;
            } else {
                int o = cb - 9 * FO;
                float4 va = make_float4(a0.x + bsh[o],   a0.y + bsh[o+1],
                                        a1.x + bsh[o+2], a1.y + bsh[o+3]);
                float4 vb = make_float4(a2.x + bsh[o+4], a2.y + bsh[o+5],
                                        a3.x + bsh[o+6], a3.y + bsh[o+7]);
                Av[o / 4]     = va;
                Av[o / 4 + 1] = vb;
            }
        }
    }
}

// ---------------- k2: fused two-level scan (40 blocks x 512, 1 gridbar) ----------------
__global__ __launch_bounds__(512) void k_scanAB()
{
    __shared__ int wred[16];
    __shared__ int bs[40];
    __shared__ int base;
    __shared__ int wsum[16];
    int t = threadIdx.x;
    int lane = t & 31, w = t >> 5;
    int b = blockIdx.x;
    int epoch = 0;

    int idx = b * 500 + t;
    int d = (t < 500 && idx < N_NODES) ? g_deg[idx] : 0;

    {
        int s = d;
#pragma unroll
        for (int off = 16; off >= 1; off >>= 1)
            s += __shfl_down_sync(0xffffffffu, s, off);
        if (lane == 0) wred[w] = s;
        __syncthreads();
        if (w == 0) {
            int v = (lane < 16) ? wred[lane] : 0;
#pragma unroll
            for (int off = 8; off >= 1; off >>= 1)
                v += __shfl_down_sync(0xffffffffu, v, off);
            if (lane == 0) g_bsum[b] = v;
        }
    }
    gridbar(&g_barS, epoch, 40);

    if (t < 40) bs[t] = g_bsum[t];
    __syncthreads();
    if (t == 0) {
        int s = 0;
#pragma unroll
        for (int i = 0; i < 40; i++) if (i < b) s += bs[i];
        base = s;
    }
    int sc = d;
#pragma unroll
    for (int off = 1; off < 32; off <<= 1) {
        int n = __shfl_up_sync(0xffffffffu, sc, off);
        if (lane >= off) sc += n;
    }
    if (lane == 31) wsum[w] = sc;
    __syncthreads();
    if (w == 0) {
        int v = (lane < 16) ? wsum[lane] : 0;
#pragma unroll
        for (int off = 1; off < 16; off <<= 1) {
            int n = __shfl_up_sync(0xffffffffu, v, off);
            if (lane >= off) v += n;
        }
        if (lane < 16) wsum[lane] = v;
    }
    __syncthreads();
    int wbase = (w == 0) ? 0 : wsum[w - 1];
    if (t < 500 && idx < N_NODES) g_cursor[idx] = base + wbase + sc - d;
}

// ---------------- k3: scatter (1 edge/thread; e converted to fp16) ----------------
__global__ void k_scatter(const int2* __restrict__ ei, const float4* __restrict__ e4) {
    int i = blockIdx.x * blockDim.x + threadIdx.x;
    if (i < N_EDGES) {
        int2 st = ei[i];
        float4 a = e4[2 * i], b = e4[2 * i + 1];
        union { __half2 h2[4]; uint4 u; } pk;
        pk.h2[0] = __floats2half2_rn(a.x, a.y);
        pk.h2[1] = __floats2half2_rn(a.z, a.w);
        pk.h2[2] = __floats2half2_rn(b.x, b.y);
        pk.h2[3] = __floats2half2_rn(b.z, b.w);
        int p = atomicAdd(&g_cursor[st.x], 1);
        g_srt[p] = st;
        reinterpret_cast<uint4*>(g_eperm_h)[p] = pk.u;
    }
}

// ---------------- node kernel layers 2/3: 480 thr = 32 nodes x 15 colgroups ----------------
// h staged in SMEM (low regs, high occupancy). COLS=240: [0,216) P̄ fp16, [216,240) AGG.
template <int LAYER, int FI>
__global__ __launch_bounds__(480) void k_node24(
    const float* __restrict__ We, const float* __restrict__ be,
    const float* __restrict__ root, const float* __restrict__ bias)
{
    constexpr int FO = 24;
    constexpr int PITCH = FI + 1;
    __shared__ __align__(16) float Wsh[FI * 240];
    __shared__ float hsh[32 * PITCH];
    __shared__ float bs[FO];
    int t = threadIdx.x;
    int nodeBase = blockIdx.x * 32;

    const float* hin = (LAYER == 2) ? g_AGG1 : g_AGG2;
    float* AGG       = (LAYER == 2) ? g_AGG2 : g_AGG3;

    // stage weights
    for (int idx = t; idx < FI * 240; idx += 480) {
        int f = idx / 240, c = idx % 240;
        float w;
        if (c < 192)      w = We[(c / 24) * (FI * 24) + f * 24 + (c % 24)];
        else if (c < 216) w = be[f * 24 + (c - 192)];
        else              w = root[f * 24 + (c - 216)];
        Wsh[idx] = w;
    }
    if (t < FO) bs[t] = bias[t];
    // stage h (relu applied)
    for (int idx = t; idx < 32 * FI; idx += 480) {
        int nl = idx / FI, f = idx % FI;
        hsh[nl * PITCH + f] = fmaxf(hin[(size_t)(nodeBase + nl) * FI + f], 0.0f);
    }
    __syncthreads();

    int nl = t & 31;       // node within block (warp = 32 nodes, same colgroup)
    int cg = t >> 5;       // colgroup 0..14
    int node = nodeBase + nl;   // grid 625*32 == N_NODES exactly

    const ulonglong2* Wv = reinterpret_cast<const ulonglong2*>(Wsh);
    uint4* Pv = reinterpret_cast<uint4*>(g_Ph) + (size_t)node * 27;   // 216/8
    float4* Av = reinterpret_cast<float4*>(AGG) + (size_t)node * 6;

    unsigned long long acc[8];
#pragma unroll
    for (int k = 0; k < 8; k++) acc[k] = 0ull;
#pragma unroll 8
    for (int f = 0; f < FI; f++) {
        const ulonglong2* wrow = Wv + f * 60 + cg * 4;
        ulonglong2 wA = wrow[0], wB = wrow[1], wC = wrow[2], wD = wrow[3];
        unsigned long long ha = packf2(hsh[nl * PITCH + f]);
        ffma2(acc[0], ha, wA.x); ffma2(acc[1], ha, wA.y);
        ffma2(acc[2], ha, wB.x); ffma2(acc[3], ha, wB.y);
        ffma2(acc[4], ha, wC.x); ffma2(acc[5], ha, wC.y);
        ffma2(acc[6], ha, wD.x); ffma2(acc[7], ha, wD.y);
    }
#pragma unroll
    for (int q2 = 0; q2 < 2; q2++) {
        int cb = cg * 16 + q2 * 8;
        float2 a0 = unpackf2(acc[4*q2+0]), a1 = unpackf2(acc[4*q2+1]);
        float2 a2 = unpackf2(acc[4*q2+2]), a3 = unpackf2(acc[4*q2+3]);
        if (cb < 216) {
            union { __half2 h2[4]; uint4 u; } pk;
            pk.h2[0] = __floats2half2_rn(a0.x, a0.y);
            pk.h2[1] = __floats2half2_rn(a1.x, a1.y);
            pk.h2[2] = __floats2half2_rn(a2.x, a2.y);
            pk.h2[3] = __floats2half2_rn(a3.x, a3.y);
            Pv[cb / 8] = pk.u;
        } else {
            int o = cb - 216;
            float4 va = make_float4(a0.x + bs[o],   a0.y + bs[o+1],
                                    a1.x + bs[o+2], a1.y + bs[o+3]);
            float4 vb = make_float4(a2.x + bs[o+4], a2.y + bs[o+5],
                                    a3.x + bs[o+6], a3.y + bs[o+7]);
            Av[o / 4]     = va;
            Av[o / 4 + 1] = vb;
        }
    }
}

// ---------------- edge kernel, layer 1: TPE=5, uint2 chunks (32 regs, occ ~80%) ----------------
__global__ __launch_bounds__(256) void k_edge1()
{
    constexpr int FO = 40, FO4 = 10, TPE = 5, CH = 2;
    int gid = blockIdx.x * 256 + threadIdx.x;
    int edge = gid / TPE;
    if (edge >= N_EDGES) return;
    int part = gid - edge * TPE;

    int2 st = g_srt[edge];
    uint4 eu = reinterpret_cast<const uint4*>(g_eperm_h)[edge];
    float2 e01 = __half22float2(*reinterpret_cast<__half2*>(&eu.x));
    float2 e23 = __half22float2(*reinterpret_cast<__half2*>(&eu.y));
    float2 e45 = __half22float2(*reinterpret_cast<__half2*>(&eu.z));
    float2 e67 = __half22float2(*reinterpret_cast<__half2*>(&eu.w));

    const uint2* P = reinterpret_cast<const uint2*>(g_Ph)
                     + (size_t)st.x * (9 * FO4) + part * CH;
    float* dst = g_AGG1 + (size_t)st.y * FO + part * CH * 4;

#pragma unroll
    for (int c = 0; c < CH; c++) {
        float4 m;
        {   // R term (s=8)
            uint2 u = P[8 * FO4 + c];
            float2 f0 = __half22float2(*reinterpret_cast<__half2*>(&u.x));
            float2 f1 = __half22float2(*reinterpret_cast<__half2*>(&u.y));
            m = make_float4(f0.x, f0.y, f1.x, f1.y);
        }
#define ACC_TERM(ES, SI) { \
        uint2 u = P[(SI) * FO4 + c]; \
        float2 f0 = __half22float2(*reinterpret_cast<__half2*>(&u.x)); \
        float2 f1 = __half22float2(*reinterpret_cast<__half2*>(&u.y)); \
        m.x += (ES) * f0.x; m.y += (ES) * f0.y; \
        m.z += (ES) * f1.x; m.w += (ES) * f1.y; }
        ACC_TERM(e01.x, 0) ACC_TERM(e01.y, 1) ACC_TERM(e23.x, 2) ACC_TERM(e23.y, 3)
        ACC_TERM(e45.x, 4) ACC_TERM(e45.y, 5) ACC_TERM(e67.x, 6) ACC_TERM(e67.y, 7)
#undef ACC_TERM
        asm volatile("red.global.add.v4.f32 [%0], {%1,%2,%3,%4};"
                     :: "l"(dst + c * 4), "f"(m.x), "f"(m.y), "f"(m.z), "f"(m.w)
                     : "memory");
    }
}

// ---------------- edge kernel, layers 2/3: TPE=3, one uint4 per slot ----------------
template <int LAYER>
__global__ __launch_bounds__(256) void k_edge24()
{
    constexpr int FO = 24, FO8 = 3, TPE = 3;
    int gid = blockIdx.x * 256 + threadIdx.x;
    int edge = gid / TPE;
    if (edge >= N_EDGES) return;
    int part = gid - edge * TPE;

    int2 st = g_srt[edge];
    uint4 eu = reinterpret_cast<const uint4*>(g_eperm_h)[edge];
    float2 e01 = __half22float2(*reinterpret_cast<__half2*>(&eu.x));
    float2 e23 = __half22float2(*reinterpret_cast<__half2*>(&eu.y));
    float2 e45 = __half22float2(*reinterpret_cast<__half2*>(&eu.z));
    float2 e67 = __half22float2(*reinterpret_cast<__half2*>(&eu.w));

    const uint4* P = reinterpret_cast<const uint4*>(g_Ph)
                     + (size_t)st.x * (9 * FO8) + part;
    float* AGG = (LAYER == 2) ? g_AGG2 : g_AGG3;
    float* dst = AGG + (size_t)st.y * FO + part * 8;

    float4 m0, m1;
    h8_to_f8(P[8 * FO8], m0, m1);   // R term
#define ACC_TERM(ES, SI) { \
    float4 p0, p1; \
    h8_to_f8(P[(SI) * FO8], p0, p1); \
    m0.x += (ES) * p0.x; m0.y += (ES) * p0.y; m0.z += (ES) * p0.z; m0.w += (ES) * p0.w; \
    m1.x += (ES) * p1.x; m1.y += (ES) * p1.y; m1.z += (ES) * p1.z; m1.w += (ES) * p1.w; }
    ACC_TERM(e01.x, 0) ACC_TERM(e01.y, 1) ACC_TERM(e23.x, 2) ACC_TERM(e23.y, 3)
    ACC_TERM(e45.x, 4) ACC_TERM(e45.y, 5) ACC_TERM(e67.x, 6) ACC_TERM(e67.y, 7)
#undef ACC_TERM
    asm volatile("red.global.add.v4.f32 [%0], {%1,%2,%3,%4};"
                 :: "l"(dst), "f"(m0.x), "f"(m0.y), "f"(m0.z), "f"(m0.w) : "memory");
    asm volatile("red.global.add.v4.f32 [%0], {%1,%2,%3,%4};"
                 :: "l"(dst + 4), "f"(m1.x), "f"(m1.y), "f"(m1.z), "f"(m1.w) : "memory");
}

// ---------------- mega kernel: pool + whole MLP (64 x 512, 3 gridbars) ----------------
__global__ __launch_bounds__(512) void k_mega(
    const float* __restrict__ Wd1, const float* __restrict__ bd1,
    const float* __restrict__ Wd2, const float* __restrict__ bd2,
    const float* __restrict__ Wd3, const float* __restrict__ bd3,
    const float* __restrict__ Wd4, const float* __restrict__ bd4,
    const float* __restrict__ Wd5, const float* __restrict__ bd5,
    const float* __restrict__ Wd6, const float* __restrict__ bd6,
    float* __restrict__ out)
{
    __shared__ float w3s[256 * 12];
    __shared__ float w4s[768 * 8];
    __shared__ float w5s[512];
    __shared__ float a2[256];
    __shared__ float a3[768];
    __shared__ float v0[24];
    __shared__ float a1[96];
    __shared__ float poolacc[21][24];
    __shared__ float bd3s[12], bd4s[8];
    __shared__ float red8[8];

    int t = threadIdx.x;
    int b = blockIdx.x;
    int epoch = 0;

    // zero g_deg for next call's hist
    for (int i = b * 512 + t; i < N_NODES; i += MEGA_NB * 512) g_deg[i] = 0;

    for (int idx = t; idx < 256 * 12; idx += 512) {
        int i = idx / 12, j = idx % 12;
        w3s[idx] = Wd3[i * 768 + b * 12 + j];
    }
    for (int idx = t; idx < 768 * 8; idx += 512) {
        int i = idx / 8, j = idx % 8;
        w4s[idx] = Wd4[i * 512 + b * 8 + j];
    }
    if (t < 512) w5s[t] = Wd5[t * 64 + b];
    if (t < 12) bd3s[t] = bd3[b * 12 + t];
    if (t < 8)  bd4s[t] = bd4[b * 8 + t];
    float bd5b = bd5[b];
    float wd6b = Wd6[b];

    // phase P: pool partials (21 row-slots per block)
    {
        int c = t % 24, slot = t / 24;
        if (slot < 21) {
            float local = 0.0f;
            for (int r = b * 21 + slot; r < N_NODES; r += MEGA_NB * 21)
                local += fmaxf(__ldcg(&g_AGG3[r * 24 + c]), 0.0f);
            poolacc[slot][c] = local;
        }
        __syncthreads();
        if (t < 24) {
            float s = 0.0f;
#pragma unroll
            for (int k = 0; k < 21; k++) s += poolacc[k][t];
            g_poolpart[b * 24 + t] = s;
        }
    }
    gridbar(&g_barcnt, epoch, MEGA_NB);   // 1

    // phase A (redundant per block): pool reduce + L1 (24->96) + L2 (96->256)
    if (t < 24) {
        float s = 0.0f;
        for (int k = 0; k < MEGA_NB; k++) s += __ldcg(&g_poolpart[k * 24 + t]);
        v0[t] = s;
    }
    __syncthreads();
    if (t < 96) {
        float acc = bd1[t];
#pragma unroll
        for (int i = 0; i < 24; i++) acc += v0[i] * Wd1[i * 96 + t];
        a1[t] = fmaxf(acc, 0.0f);
    }
    __syncthreads();
    if (t < 256) {
        float acc = bd2[t];
#pragma unroll 8
        for (int i = 0; i < 96; i++) acc += a1[i] * Wd2[i * 256 + t];
        a2[t] = fmaxf(acc, 0.0f);
    }
    __syncthreads();

    // phase B: L3 256->768, 12 outputs per block (16 threads each)
    if (t < 192) {
        int jj = t >> 4, kk = t & 15;
        float acc = 0.0f;
#pragma unroll
        for (int r = 0; r < 16; r++) {
            int i = kk + 16 * r;
            acc += a2[i] * w3s[i * 12 + jj];
        }
#pragma unroll
        for (int off = 8; off >= 1; off >>= 1)
            acc += __shfl_down_sync(0xffffffffu, acc, off, 16);
        if (kk == 0) g_v2[b * 12 + jj] = fmaxf(acc + bd3s[jj], 0.0f);
    }
    gridbar(&g_barcnt, epoch, MEGA_NB);   // 2

    // phase C: L4 768->512, 8 outputs per block
    if (t < 256) {
#pragma unroll
        for (int k = 0; k < 3; k++) a3[t + k * 256] = __ldcg(&g_v2[t + k * 256]);
    }
    __syncthreads();
    if (t < 256) {
        int w = t >> 5, l = t & 31;
        float acc = 0.0f;
#pragma unroll
        for (int k = 0; k < 24; k++) {
            int i = l + 32 * k;
            acc += a3[i] * w4s[i * 8 + w];
        }
#pragma unroll
        for (int off = 16; off >= 1; off >>= 1)
            acc += __shfl_down_sync(0xffffffffu, acc, off);
        if (l == 0) g_v3[b * 8 + w] = fmaxf(acc + bd4s[w], 0.0f);
    }
    gridbar(&g_barcnt, epoch, MEGA_NB);   // 3

    // phase D: L5 512->64 (output b) * W6[b]; last-done block finishes.
    if (t < 256) {
        float acc = __ldcg(&g_v3[t]) * w5s[t] + __ldcg(&g_v3[t + 256]) * w5s[t + 256];
#pragma unroll
        for (int off = 16; off >= 1; off >>= 1)
            acc += __shfl_down_sync(0xffffffffu, acc, off);
        int w = t >> 5, l = t & 31;
        if (l == 0) red8[w] = acc;
    }
    __syncthreads();
    if (t == 0) {
        float s = 0.0f;
#pragma unroll
        for (int k = 0; k < 8; k++) s += red8[k];
        g_v3r[b] = fmaxf(s + bd5b, 0.0f) * wd6b;
        __threadfence();
        unsigned ticket = atomicAdd(&g_done, 1u);
        if (ticket == MEGA_NB - 1) {
            float tot = bd6[0];
#pragma unroll
            for (int k = 0; k < 64; k++) tot += __ldcg(&g_v3r[k]);
            out[0] = tot;
        }
    }
}

// ---------------- launcher ----------------
extern "C" void kernel_launch(void* const* d_in, const int* in_sizes, int n_in,
                              void* d_out, int out_size)
{
    const float* x    = (const float*)d_in[0];
    const int*   ei   = (const int*)d_in[1];
    const float* e    = (const float*)d_in[2];
    const float* We1  = (const float*)d_in[3];
    const float* be1  = (const float*)d_in[4];
    const float* root1= (const float*)d_in[5];
    const float* b1   = (const float*)d_in[6];
    const float* We2  = (const float*)d_in[7];
    const float* be2  = (const float*)d_in[8];
    const float* root2= (const float*)d_in[9];
    const float* b2   = (const float*)d_in[10];
    const float* We3  = (const float*)d_in[11];
    const float* be3  = (const float*)d_in[12];
    const float* root3= (const float*)d_in[13];
    const float* b3   = (const float*)d_in[14];
    const float* Wd1  = (const float*)d_in[15];
    const float* bd1  = (const float*)d_in[16];
    const float* Wd2  = (const float*)d_in[17];
    const float* bd2  = (const float*)d_in[18];
    const float* Wd3  = (const float*)d_in[19];
    const float* bd3  = (const float*)d_in[20];
    const float* Wd4  = (const float*)d_in[21];
    const float* bd4  = (const float*)d_in[22];
    const float* Wd5  = (const float*)d_in[23];
    const float* bd5  = (const float*)d_in[24];
    const float* Wd6  = (const float*)d_in[25];
    const float* bd6  = (const float*)d_in[26];

    const int2* ei2 = (const int2*)ei;
    const float4* e4 = (const float4*)e;

    const int flat_grid = (N_EDGES + 255) / 256;             // 625
    const int edge_grid40 = (5 * N_EDGES + 255) / 256;       // 3125
    const int edge_grid24 = (3 * N_EDGES + 255) / 256;       // 1875
    const int node24_grid = N_NODES / 32;                    // 625

    k1_node1_hist<<<395 + 625, 256>>>(x, We1, be1, root1, b1, ei2);
    k_scanAB<<<40, 512>>>();
    k_scatter<<<flat_grid, 256>>>(ei2, e4);
    k_edge1<<<edge_grid40, 256>>>();
    k_node24<2, 40><<<node24_grid, 480>>>(We2, be2, root2, b2);
    k_edge24<2><<<edge_grid24, 256>>>();
    k_node24<3, 24><<<node24_grid, 480>>>(We3, be3, root3, b3);
    k_edge24<3><<<edge_grid24, 256>>>();
    k_mega<<<MEGA_NB, 512>>>(Wd1, bd1, Wd2, bd2, Wd3, bd3, Wd4, bd4, Wd5, bd5,
                             Wd6, bd6, (float*)d_out);
}

// round 17
// speedup vs baseline: 1.1167x; 1.1167x over previous
#include <cuda_runtime.h>
#include <cuda_fp16.h>

// ---------------- problem constants ----------------
#define N_NODES 20000
#define N_EDGES 160000
#define MEGA_NB 64

// ---------------- device scratch (static; no allocs) ----------------
// P̄[n, s, o]: s=0..7 edge-weight slots, s=8 = R (unit coefficient). fp16.
__device__ __align__(16) __half g_Ph[N_NODES * 360];  // max 9*40 cols
__device__ __align__(16) float g_AGG1[N_NODES * 40];
__device__ __align__(16) float g_AGG2[N_NODES * 24];
__device__ __align__(16) float g_AGG3[N_NODES * 24];
__device__ int   g_deg[N_NODES];    // zero at load; re-zeroed by k_mega each call
__device__ int   g_cursor[N_NODES];
__device__ int   g_bsum[40];
__device__ __align__(8)  int2   g_srt[N_EDGES];       // (src, tgt) sorted by src
__device__ __align__(16) __half g_eperm_h[N_EDGES * 8];  // e payload fp16, src-sorted
__device__ float g_poolpart[MEGA_NB * 24];
__device__ __align__(16) float g_v2[768];
__device__ __align__(16) float g_v3[512];
__device__ float g_v3r[64];
__device__ unsigned g_barS;    // scanAB barrier
__device__ unsigned g_barcnt;  // mega barrier
__device__ unsigned g_done;    // mega last-block ticket

// ---------------- helpers ----------------
__device__ __forceinline__ void ffma2(unsigned long long& d, unsigned long long a,
                                      unsigned long long b) {
    asm("fma.rn.f32x2 %0, %1, %2, %0;" : "+l"(d) : "l"(a), "l"(b));
}
__device__ __forceinline__ unsigned long long packf2(float x) {
    unsigned long long r;
    asm("mov.b64 %0, {%1, %1};" : "=l"(r) : "f"(x));
    return r;
}
__device__ __forceinline__ float2 unpackf2(unsigned long long v) {
    float2 f;
    asm("mov.b64 {%0, %1}, %2;" : "=f"(f.x), "=f"(f.y) : "l"(v));
    return f;
}
// unpack 8 fp16 (uint4) -> two float4
__device__ __forceinline__ void h8_to_f8(uint4 u, float4& a, float4& b) {
    float2 f0 = __half22float2(*reinterpret_cast<__half2*>(&u.x));
    float2 f1 = __half22float2(*reinterpret_cast<__half2*>(&u.y));
    float2 f2 = __half22float2(*reinterpret_cast<__half2*>(&u.z));
    float2 f3 = __half22float2(*reinterpret_cast<__half2*>(&u.w));
    a = make_float4(f0.x, f0.y, f1.x, f1.y);
    b = make_float4(f2.x, f2.y, f3.x, f3.y);
}
__device__ __forceinline__ void gridbar(unsigned* cnt, int& epoch, int nb) {
    __threadfence();
    __syncthreads();
    epoch++;
    if (threadIdx.x == 0) {
        atomicAdd(cnt, 1u);
        unsigned target = (unsigned)epoch * (unsigned)nb;
        while (*((volatile unsigned*)cnt) < target) __nanosleep(20);
    }
    __syncthreads();
}

// ---------------- k1: node1 (blocks 0..394) || hist (blocks 395..1019) ----------------
// node1: cols [0,360) P̄(fp16, incl. R at s=8), [360,400) AGG1(+bias).
__global__ __launch_bounds__(256) void k1_node1_hist(
    const float* __restrict__ xin,
    const float* __restrict__ We, const float* __restrict__ be,
    const float* __restrict__ root, const float* __restrict__ bias,
    const int2* __restrict__ ei)
{
    constexpr int FI = 16, FO = 40, CC = 5;
    constexpr int CC16 = CC * 16;
    __shared__ __align__(16) float Wsh[FI * CC16];
    __shared__ float bsh[FO];
    int t = threadIdx.x;
    int b = blockIdx.x;

    if (b >= 395) {   // histogram blocks (full 160k-thread parallelism)
        int i = (b - 395) * 256 + t;
        if (i < N_EDGES) atomicAdd(&g_deg[ei[i].x], 1);
        return;
    }

    int bx = b % 79;        // node tile
    int by = b / 79;        // col chunk
    int cg0 = by * CC;
    int colbase = cg0 * 16;

    if (b == 0 && t == 0) { g_barS = 0u; g_barcnt = 0u; g_done = 0u; }

    for (int idx = t; idx < FI * CC16; idx += 256) {
        int f = idx / CC16, cl = idx % CC16;
        int c = colbase + cl;
        float w;
        if (c < 8 * FO) {
            int s = c / FO, o = c % FO;
            w = We[s * (FI * FO) + f * FO + o];
        } else if (c < 9 * FO) {
            int o = c - 8 * FO;
            w = be[f * FO + o];
        } else {
            int o = c - 9 * FO;
            w = root[f * FO + o];
        }
        Wsh[idx] = w;
    }
    for (int idx = t; idx < FO; idx += 256) bsh[idx] = bias[idx];
    __syncthreads();

    int node = bx * 256 + t;
    if (node >= N_NODES) return;

    float h[FI];
    const float4* hv = reinterpret_cast<const float4*>(xin + (size_t)node * FI);
#pragma unroll
    for (int f4 = 0; f4 < FI / 4; f4++) {
        float4 a = hv[f4];
        h[4*f4+0]=a.x; h[4*f4+1]=a.y; h[4*f4+2]=a.z; h[4*f4+3]=a.w;
    }

    const ulonglong2* Wv = reinterpret_cast<const ulonglong2*>(Wsh);
    uint4* Pv = reinterpret_cast<uint4*>(g_Ph) + (size_t)node * (9 * FO / 8);
    float4* Av = reinterpret_cast<float4*>(g_AGG1) + (size_t)node * (FO / 4);

#pragma unroll
    for (int cg = 0; cg < CC; cg++) {
        unsigned long long acc[8];
#pragma unroll
        for (int k = 0; k < 8; k++) acc[k] = 0ull;
#pragma unroll
        for (int f = 0; f < FI; f++) {
            const ulonglong2* wrow = Wv + f * (CC * 4) + cg * 4;
            ulonglong2 wA = wrow[0], wB = wrow[1], wC = wrow[2], wD = wrow[3];
            unsigned long long ha = packf2(h[f]);
            ffma2(acc[0], ha, wA.x); ffma2(acc[1], ha, wA.y);
            ffma2(acc[2], ha, wB.x); ffma2(acc[3], ha, wB.y);
            ffma2(acc[4], ha, wC.x); ffma2(acc[5], ha, wC.y);
            ffma2(acc[6], ha, wD.x); ffma2(acc[7], ha, wD.y);
        }
#pragma unroll
        for (int q2 = 0; q2 < 2; q2++) {   // 8 cols per store group
            int cb = (cg0 + cg) * 16 + q2 * 8;
            float2 a0 = unpackf2(acc[4*q2+0]), a1 = unpackf2(acc[4*q2+1]);
            float2 a2 = unpackf2(acc[4*q2+2]), a3 = unpackf2(acc[4*q2+3]);
            if (cb < 9 * FO) {
                union { __half2 h2[4]; uint4 u; } pk;
                pk.h2[0] = __floats2half2_rn(a0.x, a0.y);
                pk.h2[1] = __floats2half2_rn(a1.x, a1.y);
                pk.h2[2] = __floats2half2_rn(a2.x, a2.y);
                pk.h2[3] = __floats2half2_rn(a3.x, a3.y);
                Pv[cb / 8] = pk.u;
            } else {
                int o = cb - 9 * FO;
                float4 va = make_float4(a0.x + bsh[o],   a0.y + bsh[o+1],
                                        a1.x + bsh[o+2], a1.y + bsh[o+3]);
                float4 vb = make_float4(a2.x + bsh[o+4], a2.y + bsh[o+5],
                                        a3.x + bsh[o+6], a3.y + bsh[o+7]);
                Av[o / 4]     = va;
                Av[o / 4 + 1] = vb;
            }
        }
    }
}

// ---------------- k2: fused two-level scan (40 blocks x 512, 1 gridbar) ----------------
__global__ __launch_bounds__(512) void k_scanAB()
{
    __shared__ int wred[16];
    __shared__ int bs[40];
    __shared__ int base;
    __shared__ int wsum[16];
    int t = threadIdx.x;
    int lane = t & 31, w = t >> 5;
    int b = blockIdx.x;
    int epoch = 0;

    int idx = b * 500 + t;
    int d = (t < 500 && idx < N_NODES) ? g_deg[idx] : 0;

    {
        int s = d;
#pragma unroll
        for (int off = 16; off >= 1; off >>= 1)
            s += __shfl_down_sync(0xffffffffu, s, off);
        if (lane == 0) wred[w] = s;
        __syncthreads();
        if (w == 0) {
            int v = (lane < 16) ? wred[lane] : 0;
#pragma unroll
            for (int off = 8; off >= 1; off >>= 1)
                v += __shfl_down_sync(0xffffffffu, v, off);
            if (lane == 0) g_bsum[b] = v;
        }
    }
    gridbar(&g_barS, epoch, 40);

    if (t < 40) bs[t] = g_bsum[t];
    __syncthreads();
    if (t == 0) {
        int s = 0;
#pragma unroll
        for (int i = 0; i < 40; i++) if (i < b) s += bs[i];
        base = s;
    }
    int sc = d;
#pragma unroll
    for (int off = 1; off < 32; off <<= 1) {
        int n = __shfl_up_sync(0xffffffffu, sc, off);
        if (lane >= off) sc += n;
    }
    if (lane == 31) wsum[w] = sc;
    __syncthreads();
    if (w == 0) {
        int v = (lane < 16) ? wsum[lane] : 0;
#pragma unroll
        for (int off = 1; off < 16; off <<= 1) {
            int n = __shfl_up_sync(0xffffffffu, v, off);
            if (lane >= off) v += n;
        }
        if (lane < 16) wsum[lane] = v;
    }
    __syncthreads();
    int wbase = (w == 0) ? 0 : wsum[w - 1];
    if (t < 500 && idx < N_NODES) g_cursor[idx] = base + wbase + sc - d;
}

// ---------------- k3: scatter (1 edge/thread; e converted to fp16) ----------------
__global__ void k_scatter(const int2* __restrict__ ei, const float4* __restrict__ e4) {
    int i = blockIdx.x * blockDim.x + threadIdx.x;
    if (i < N_EDGES) {
        int2 st = ei[i];
        float4 a = e4[2 * i], b = e4[2 * i + 1];
        union { __half2 h2[4]; uint4 u; } pk;
        pk.h2[0] = __floats2half2_rn(a.x, a.y);
        pk.h2[1] = __floats2half2_rn(a.z, a.w);
        pk.h2[2] = __floats2half2_rn(b.x, b.y);
        pk.h2[3] = __floats2half2_rn(b.z, b.w);
        int p = atomicAdd(&g_cursor[st.x], 1);
        g_srt[p] = st;
        reinterpret_cast<uint4*>(g_eperm_h)[p] = pk.u;
    }
}

// ---------------- node kernel (layers 2/3): low-reg, h streamed per colgroup ----------------
// grid (79 node-tiles, 5 col-chunks of CC=3 groups); 256 thr, 1 node/thread.
template <int LAYER, int FI, int FO, int CC>
__global__ __launch_bounds__(256) void k_node(
    const float* __restrict__ We, const float* __restrict__ be,
    const float* __restrict__ root, const float* __restrict__ bias)
{
    constexpr int CC16 = CC * 16;
    __shared__ __align__(16) float Wsh[FI * CC16];
    __shared__ float bsh[FO];
    int t = threadIdx.x;
    int cg0 = blockIdx.y * CC;
    int colbase = cg0 * 16;

    for (int idx = t; idx < FI * CC16; idx += 256) {
        int f = idx / CC16, cl = idx % CC16;
        int c = colbase + cl;
        float w;
        if (c < 8 * FO) {
            int s = c / FO, o = c % FO;
            w = We[s * (FI * FO) + f * FO + o];
        } else if (c < 9 * FO) {
            int o = c - 8 * FO;
            w = be[f * FO + o];
        } else {
            int o = c - 9 * FO;
            w = root[f * FO + o];
        }
        Wsh[idx] = w;
    }
    for (int idx = t; idx < FO; idx += 256) bsh[idx] = bias[idx];
    __syncthreads();

    int node = blockIdx.x * 256 + t;
    if (node >= N_NODES) return;

    const float* hin = (LAYER == 2) ? g_AGG1 : g_AGG2;
    float* AGG       = (LAYER == 2) ? g_AGG2 : g_AGG3;
    const float4* hv = reinterpret_cast<const float4*>(hin + (size_t)node * FI);

    const ulonglong2* Wv = reinterpret_cast<const ulonglong2*>(Wsh);
    uint4* Pv = reinterpret_cast<uint4*>(g_Ph) + (size_t)node * (9 * FO / 8);
    float4* Av = reinterpret_cast<float4*>(AGG) + (size_t)node * (FO / 4);

#pragma unroll
    for (int cg = 0; cg < CC; cg++) {
        unsigned long long acc[8];
#pragma unroll
        for (int k = 0; k < 8; k++) acc[k] = 0ull;
#pragma unroll
        for (int f4 = 0; f4 < FI / 4; f4++) {
            float4 hh = hv[f4];   // L1-resident after first cg
            hh.x = fmaxf(hh.x, 0.f); hh.y = fmaxf(hh.y, 0.f);
            hh.z = fmaxf(hh.z, 0.f); hh.w = fmaxf(hh.w, 0.f);
            float hc[4] = {hh.x, hh.y, hh.z, hh.w};
#pragma unroll
            for (int j = 0; j < 4; j++) {
                int f = 4 * f4 + j;
                const ulonglong2* wrow = Wv + f * (CC * 4) + cg * 4;
                ulonglong2 wA = wrow[0], wB = wrow[1], wC = wrow[2], wD = wrow[3];
                unsigned long long ha = packf2(hc[j]);
                ffma2(acc[0], ha, wA.x); ffma2(acc[1], ha, wA.y);
                ffma2(acc[2], ha, wB.x); ffma2(acc[3], ha, wB.y);
                ffma2(acc[4], ha, wC.x); ffma2(acc[5], ha, wC.y);
                ffma2(acc[6], ha, wD.x); ffma2(acc[7], ha, wD.y);
            }
        }
#pragma unroll
        for (int q2 = 0; q2 < 2; q2++) {
            int cb = (cg0 + cg) * 16 + q2 * 8;
            float2 a0 = unpackf2(acc[4*q2+0]), a1 = unpackf2(acc[4*q2+1]);
            float2 a2 = unpackf2(acc[4*q2+2]), a3 = unpackf2(acc[4*q2+3]);
            if (cb < 9 * FO) {
                union { __half2 h2[4]; uint4 u; } pk;
                pk.h2[0] = __floats2half2_rn(a0.x, a0.y);
                pk.h2[1] = __floats2half2_rn(a1.x, a1.y);
                pk.h2[2] = __floats2half2_rn(a2.x, a2.y);
                pk.h2[3] = __floats2half2_rn(a3.x, a3.y);
                Pv[cb / 8] = pk.u;
            } else {
                int o = cb - 9 * FO;
                float4 va = make_float4(a0.x + bsh[o],   a0.y + bsh[o+1],
                                        a1.x + bsh[o+2], a1.y + bsh[o+3]);
                float4 vb = make_float4(a2.x + bsh[o+4], a2.y + bsh[o+5],
                                        a3.x + bsh[o+6], a3.y + bsh[o+7]);
                Av[o / 4]     = va;
                Av[o / 4 + 1] = vb;
            }
        }
    }
}

// ---------------- edge kernel, layer 1: TPE=5, uint2 chunks (32 regs, occ ~80%) ----------------
__global__ __launch_bounds__(256) void k_edge1()
{
    constexpr int FO = 40, FO4 = 10, TPE = 5, CH = 2;
    int gid = blockIdx.x * 256 + threadIdx.x;
    int edge = gid / TPE;
    if (edge >= N_EDGES) return;
    int part = gid - edge * TPE;

    int2 st = g_srt[edge];
    uint4 eu = reinterpret_cast<const uint4*>(g_eperm_h)[edge];
    float2 e01 = __half22float2(*reinterpret_cast<__half2*>(&eu.x));
    float2 e23 = __half22float2(*reinterpret_cast<__half2*>(&eu.y));
    float2 e45 = __half22float2(*reinterpret_cast<__half2*>(&eu.z));
    float2 e67 = __half22float2(*reinterpret_cast<__half2*>(&eu.w));

    const uint2* P = reinterpret_cast<const uint2*>(g_Ph)
                     + (size_t)st.x * (9 * FO4) + part * CH;
    float* dst = g_AGG1 + (size_t)st.y * FO + part * CH * 4;

#pragma unroll
    for (int c = 0; c < CH; c++) {
        float4 m;
        {   // R term (s=8)
            uint2 u = P[8 * FO4 + c];
            float2 f0 = __half22float2(*reinterpret_cast<__half2*>(&u.x));
            float2 f1 = __half22float2(*reinterpret_cast<__half2*>(&u.y));
            m = make_float4(f0.x, f0.y, f1.x, f1.y);
        }
#define ACC_TERM(ES, SI) { \
        uint2 u = P[(SI) * FO4 + c]; \
        float2 f0 = __half22float2(*reinterpret_cast<__half2*>(&u.x)); \
        float2 f1 = __half22float2(*reinterpret_cast<__half2*>(&u.y)); \
        m.x += (ES) * f0.x; m.y += (ES) * f0.y; \
        m.z += (ES) * f1.x; m.w += (ES) * f1.y; }
        ACC_TERM(e01.x, 0) ACC_TERM(e01.y, 1) ACC_TERM(e23.x, 2) ACC_TERM(e23.y, 3)
        ACC_TERM(e45.x, 4) ACC_TERM(e45.y, 5) ACC_TERM(e67.x, 6) ACC_TERM(e67.y, 7)
#undef ACC_TERM
        asm volatile("red.global.add.v4.f32 [%0], {%1,%2,%3,%4};"
                     :: "l"(dst + c * 4), "f"(m.x), "f"(m.y), "f"(m.z), "f"(m.w)
                     : "memory");
    }
}

// ---------------- edge kernel, layers 2/3: TPE=3, one uint4 per slot ----------------
template <int LAYER>
__global__ __launch_bounds__(256) void k_edge24()
{
    constexpr int FO = 24, FO8 = 3, TPE = 3;
    int gid = blockIdx.x * 256 + threadIdx.x;
    int edge = gid / TPE;
    if (edge >= N_EDGES) return;
    int part = gid - edge * TPE;

    int2 st = g_srt[edge];
    uint4 eu = reinterpret_cast<const uint4*>(g_eperm_h)[edge];
    float2 e01 = __half22float2(*reinterpret_cast<__half2*>(&eu.x));
    float2 e23 = __half22float2(*reinterpret_cast<__half2*>(&eu.y));
    float2 e45 = __half22float2(*reinterpret_cast<__half2*>(&eu.z));
    float2 e67 = __half22float2(*reinterpret_cast<__half2*>(&eu.w));

    const uint4* P = reinterpret_cast<const uint4*>(g_Ph)
                     + (size_t)st.x * (9 * FO8) + part;
    float* AGG = (LAYER == 2) ? g_AGG2 : g_AGG3;
    float* dst = AGG + (size_t)st.y * FO + part * 8;

    float4 m0, m1;
    h8_to_f8(P[8 * FO8], m0, m1);   // R term
#define ACC_TERM(ES, SI) { \
    float4 p0, p1; \
    h8_to_f8(P[(SI) * FO8], p0, p1); \
    m0.x += (ES) * p0.x; m0.y += (ES) * p0.y; m0.z += (ES) * p0.z; m0.w += (ES) * p0.w; \
    m1.x += (ES) * p1.x; m1.y += (ES) * p1.y; m1.z += (ES) * p1.z; m1.w += (ES) * p1.w; }
    ACC_TERM(e01.x, 0) ACC_TERM(e01.y, 1) ACC_TERM(e23.x, 2) ACC_TERM(e23.y, 3)
    ACC_TERM(e45.x, 4) ACC_TERM(e45.y, 5) ACC_TERM(e67.x, 6) ACC_TERM(e67.y, 7)
#undef ACC_TERM
    asm volatile("red.global.add.v4.f32 [%0], {%1,%2,%3,%4};"
                 :: "l"(dst), "f"(m0.x), "f"(m0.y), "f"(m0.z), "f"(m0.w) : "memory");
    asm volatile("red.global.add.v4.f32 [%0], {%1,%2,%3,%4};"
                 :: "l"(dst + 4), "f"(m1.x), "f"(m1.y), "f"(m1.z), "f"(m1.w) : "memory");
}

// ---------------- mega kernel: pool + whole MLP (64 x 512, 3 gridbars) ----------------
__global__ __launch_bounds__(512) void k_mega(
    const float* __restrict__ Wd1, const float* __restrict__ bd1,
    const float* __restrict__ Wd2, const float* __restrict__ bd2,
    const float* __restrict__ Wd3, const float* __restrict__ bd3,
    const float* __restrict__ Wd4, const float* __restrict__ bd4,
    const float* __restrict__ Wd5, const float* __restrict__ bd5,
    const float* __restrict__ Wd6, const float* __restrict__ bd6,
    float* __restrict__ out)
{
    __shared__ float w3s[256 * 12];
    __shared__ float w4s[768 * 8];
    __shared__ float w5s[512];
    __shared__ float a2[256];
    __shared__ float a3[768];
    __shared__ float v0[24];
    __shared__ float a1[96];
    __shared__ float poolacc[21][24];
    __shared__ float bd3s[12], bd4s[8];
    __shared__ float red8[8];

    int t = threadIdx.x;
    int b = blockIdx.x;
    int epoch = 0;

    // zero g_deg for next call's hist
    for (int i = b * 512 + t; i < N_NODES; i += MEGA_NB * 512) g_deg[i] = 0;

    for (int idx = t; idx < 256 * 12; idx += 512) {
        int i = idx / 12, j = idx % 12;
        w3s[idx] = Wd3[i * 768 + b * 12 + j];
    }
    for (int idx = t; idx < 768 * 8; idx += 512) {
        int i = idx / 8, j = idx % 8;
        w4s[idx] = Wd4[i * 512 + b * 8 + j];
    }
    if (t < 512) w5s[t] = Wd5[t * 64 + b];
    if (t < 12) bd3s[t] = bd3[b * 12 + t];
    if (t < 8)  bd4s[t] = bd4[b * 8 + t];
    float bd5b = bd5[b];
    float wd6b = Wd6[b];

    // phase P: pool partials (21 row-slots per block)
    {
        int c = t % 24, slot = t / 24;
        if (slot < 21) {
            float local = 0.0f;
            for (int r = b * 21 + slot; r < N_NODES; r += MEGA_NB * 21)
                local += fmaxf(__ldcg(&g_AGG3[r * 24 + c]), 0.0f);
            poolacc[slot][c] = local;
        }
        __syncthreads();
        if (t < 24) {
            float s = 0.0f;
#pragma unroll
            for (int k = 0; k < 21; k++) s += poolacc[k][t];
            g_poolpart[b * 24 + t] = s;
        }
    }
    gridbar(&g_barcnt, epoch, MEGA_NB);   // 1

    // phase A (redundant per block): pool reduce + L1 (24->96) + L2 (96->256)
    if (t < 24) {
        float s = 0.0f;
        for (int k = 0; k < MEGA_NB; k++) s += __ldcg(&g_poolpart[k * 24 + t]);
        v0[t] = s;
    }
    __syncthreads();
    if (t < 96) {
        float acc = bd1[t];
#pragma unroll
        for (int i = 0; i < 24; i++) acc += v0[i] * Wd1[i * 96 + t];
        a1[t] = fmaxf(acc, 0.0f);
    }
    __syncthreads();
    if (t < 256) {
        float acc = bd2[t];
#pragma unroll 8
        for (int i = 0; i < 96; i++) acc += a1[i] * Wd2[i * 256 + t];
        a2[t] = fmaxf(acc, 0.0f);
    }
    __syncthreads();

    // phase B: L3 256->768, 12 outputs per block (16 threads each)
    if (t < 192) {
        int jj = t >> 4, kk = t & 15;
        float acc = 0.0f;
#pragma unroll
        for (int r = 0; r < 16; r++) {
            int i = kk + 16 * r;
            acc += a2[i] * w3s[i * 12 + jj];
        }
#pragma unroll
        for (int off = 8; off >= 1; off >>= 1)
            acc += __shfl_down_sync(0xffffffffu, acc, off, 16);
        if (kk == 0) g_v2[b * 12 + jj] = fmaxf(acc + bd3s[jj], 0.0f);
    }
    gridbar(&g_barcnt, epoch, MEGA_NB);   // 2

    // phase C: L4 768->512, 8 outputs per block
    if (t < 256) {
#pragma unroll
        for (int k = 0; k < 3; k++) a3[t + k * 256] = __ldcg(&g_v2[t + k * 256]);
    }
    __syncthreads();
    if (t < 256) {
        int w = t >> 5, l = t & 31;
        float acc = 0.0f;
#pragma unroll
        for (int k = 0; k < 24; k++) {
            int i = l + 32 * k;
            acc += a3[i] * w4s[i * 8 + w];
        }
#pragma unroll
        for (int off = 16; off >= 1; off >>= 1)
            acc += __shfl_down_sync(0xffffffffu, acc, off);
        if (l == 0) g_v3[b * 8 + w] = fmaxf(acc + bd4s[w], 0.0f);
    }
    gridbar(&g_barcnt, epoch, MEGA_NB);   // 3

    // phase D: L5 512->64 (output b) * W6[b]; last-done block finishes.
    if (t < 256) {
        float acc = __ldcg(&g_v3[t]) * w5s[t] + __ldcg(&g_v3[t + 256]) * w5s[t + 256];
#pragma unroll
        for (int off = 16; off >= 1; off >>= 1)
            acc += __shfl_down_sync(0xffffffffu, acc, off);
        int w = t >> 5, l = t & 31;
        if (l == 0) red8[w] = acc;
    }
    __syncthreads();
    if (t == 0) {
        float s = 0.0f;
#pragma unroll
        for (int k = 0; k < 8; k++) s += red8[k];
        g_v3r[b] = fmaxf(s + bd5b, 0.0f) * wd6b;
        __threadfence();
        unsigned ticket = atomicAdd(&g_done, 1u);
        if (ticket == MEGA_NB - 1) {
            float tot = bd6[0];
#pragma unroll
            for (int k = 0; k < 64; k++) tot += __ldcg(&g_v3r[k]);
            out[0] = tot;
        }
    }
}

// ---------------- launcher ----------------
extern "C" void kernel_launch(void* const* d_in, const int* in_sizes, int n_in,
                              void* d_out, int out_size)
{
    const float* x    = (const float*)d_in[0];
    const int*   ei   = (const int*)d_in[1];
    const float* e    = (const float*)d_in[2];
    const float* We1  = (const float*)d_in[3];
    const float* be1  = (const float*)d_in[4];
    const float* root1= (const float*)d_in[5];
    const float* b1   = (const float*)d_in[6];
    const float* We2  = (const float*)d_in[7];
    const float* be2  = (const float*)d_in[8];
    const float* root2= (const float*)d_in[9];
    const float* b2   = (const float*)d_in[10];
    const float* We3  = (const float*)d_in[11];
    const float* be3  = (const float*)d_in[12];
    const float* root3= (const float*)d_in[13];
    const float* b3   = (const float*)d_in[14];
    const float* Wd1  = (const float*)d_in[15];
    const float* bd1  = (const float*)d_in[16];
    const float* Wd2  = (const float*)d_in[17];
    const float* bd2  = (const float*)d_in[18];
    const float* Wd3  = (const float*)d_in[19];
    const float* bd3  = (const float*)d_in[20];
    const float* Wd4  = (const float*)d_in[21];
    const float* bd4  = (const float*)d_in[22];
    const float* Wd5  = (const float*)d_in[23];
    const float* bd5  = (const float*)d_in[24];
    const float* Wd6  = (const float*)d_in[25];
    const float* bd6  = (const float*)d_in[26];

    const int2* ei2 = (const int2*)ei;
    const float4* e4 = (const float4*)e;

    const int ntile = (N_NODES + 255) / 256;                 // 79
    const int flat_grid = (N_EDGES + 255) / 256;             // 625
    const int edge_grid40 = (5 * N_EDGES + 255) / 256;       // 3125
    const int edge_grid24 = (3 * N_EDGES + 255) / 256;       // 1875

    k1_node1_hist<<<395 + 625, 256>>>(x, We1, be1, root1, b1, ei2);
    k_scanAB<<<40, 512>>>();
    k_scatter<<<flat_grid, 256>>>(ei2, e4);
    k_edge1<<<edge_grid40, 256>>>();
    k_node<2, 40, 24, 3><<<dim3(ntile, 5), 256>>>(We2, be2, root2, b2);
    k_edge24<2><<<edge_grid24, 256>>>();
    k_node<3, 24, 24, 3><<<dim3(ntile, 5), 256>>>(We3, be3, root3, b3);
    k_edge24<3><<<edge_grid24, 256>>>();
    k_mega<<<MEGA_NB, 512>>>(Wd1, bd1, Wd2, bd2, Wd3, bd3, Wd4, bd4, Wd5, bd5,
                             Wd6, bd6, (float*)d_out);
}